// round 7
// baseline (speedup 1.0000x reference)
#include <cuda_runtime.h>
#include <cuda_bf16.h>
#include <cstdint>

#define EPS_BN 1e-5f

#define BATCH   32
#define CIN     128
#define COUT    256
#define CEXP    1024
#define HOUT    28
#define HWOUT   784
#define MPIX    25088          // BATCH*HWOUT, divisible by 128
#define KL1     512            // conv1 logical K (CIN*2*2)

// ------------- scratch (device globals) -------------------------------------
__device__ uint8_t       g_A8[(size_t)MPIX * 1024];       // [m][hi512|lo512] u8
__device__ int8_t        g_W8d[(size_t)COUT * 512];       // conv1 weights s8 [n][k]
__device__ float         g_t0[(size_t)BATCH * COUT * HWOUT]; // conv1 out NCHW
__device__ __nv_bfloat16 g_t1[(size_t)2 * COUT * MPIX];   // dw out split [2c][m]
__device__ __nv_bfloat16 g_t2[(size_t)2 * CEXP * MPIX];   // expand out split
__device__ float         g_W1f[COUT * 49];
__device__ __nv_bfloat16 g_W2[2 * COUT * CEXP];           // 15*w dup rows [2k][n]
__device__ __nv_bfloat16 g_W3[2 * CEXP * COUT];
__device__ unsigned g_max[4];

// ------------- helpers -------------------------------------------------------
__device__ __forceinline__ void ldmx4t(uint32_t& r0, uint32_t& r1, uint32_t& r2,
                                       uint32_t& r3, uint32_t addr) {
    asm volatile("ldmatrix.sync.aligned.m8n8.x4.trans.shared.b16 {%0,%1,%2,%3},[%4];"
                 : "=r"(r0), "=r"(r1), "=r"(r2), "=r"(r3) : "r"(addr));
}
__device__ __forceinline__ void ldmx4(uint32_t& r0, uint32_t& r1, uint32_t& r2,
                                      uint32_t& r3, uint32_t addr) {
    asm volatile("ldmatrix.sync.aligned.m8n8.x4.shared.b16 {%0,%1,%2,%3},[%4];"
                 : "=r"(r0), "=r"(r1), "=r"(r2), "=r"(r3) : "r"(addr));
}
__device__ __forceinline__ void mma16816(float c[4], const uint32_t a[4],
                                         uint32_t b0, uint32_t b1) {
    asm volatile("mma.sync.aligned.m16n8k16.row.col.f32.bf16.bf16.f32 "
                 "{%0,%1,%2,%3},{%4,%5,%6,%7},{%8,%9},{%0,%1,%2,%3};"
                 : "+f"(c[0]), "+f"(c[1]), "+f"(c[2]), "+f"(c[3])
                 : "r"(a[0]), "r"(a[1]), "r"(a[2]), "r"(a[3]), "r"(b0), "r"(b1));
}
__device__ __forceinline__ void imma16832(int c[4], const uint32_t a[4],
                                          uint32_t b0, uint32_t b1) {
    asm volatile("mma.sync.aligned.m16n8k32.row.col.s32.u8.s8.s32 "
                 "{%0,%1,%2,%3},{%4,%5,%6,%7},{%8,%9},{%0,%1,%2,%3};"
                 : "+r"(c[0]), "+r"(c[1]), "+r"(c[2]), "+r"(c[3])
                 : "r"(a[0]), "r"(a[1]), "r"(a[2]), "r"(a[3]), "r"(b0), "r"(b1));
}
__device__ __forceinline__ void cp16(uint32_t s, const void* g) {
    asm volatile("cp.async.cg.shared.global [%0],[%1],16;\n" :: "r"(s), "l"(g));
}
#define CP_COMMIT() asm volatile("cp.async.commit_group;\n")

// ------------- weight quantization (fused) -----------------------------------
__global__ void init_max_kernel() { if (threadIdx.x < 4) g_max[threadIdx.x] = 0u; }

__global__ void max4_kernel(const float* __restrict__ w0, const float* __restrict__ w1,
                            const float* __restrict__ w2, const float* __restrict__ w3) {
    int slot = blockIdx.y;
    const float* w; int n;
    if      (slot == 0) { w = w0; n = COUT * KL1; }
    else if (slot == 1) { w = w1; n = COUT * 49; }
    else if (slot == 2) { w = w2; n = CEXP * COUT; }
    else                { w = w3; n = COUT * CEXP; }
    float lm = 0.f;
    for (int i = blockIdx.x * blockDim.x + threadIdx.x; i < n;
         i += gridDim.x * blockDim.x)
        lm = fmaxf(lm, fabsf(tanhf(w[i])));
    #pragma unroll
    for (int o = 16; o > 0; o >>= 1)
        lm = fmaxf(lm, __shfl_xor_sync(0xffffffffu, lm, o));
    if ((threadIdx.x & 31) == 0) atomicMax(&g_max[slot], __float_as_uint(lm));
}

// y=0: Wd -> s8 [n][k] straight; y=1: W2, y=2: W3 -> bf16 [2k][n] dup;
// y=3: W1 -> fp32 true values
__global__ void quantW_all(const float* __restrict__ Wd, const float* __restrict__ W2,
                           const float* __restrict__ W3, const float* __restrict__ W1) {
    int which = blockIdx.y;
    int i = blockIdx.x * 256 + threadIdx.x;
    if (which == 0) {
        if (i >= COUT * 512) return;
        float mx = __uint_as_float(g_max[0]);
        float t = tanhf(Wd[i]) / (2.f * mx) + 0.5f;
        g_W8d[i] = (int8_t)(int)(2.f * rintf(t * 15.f) - 15.f);
        return;
    }
    if (which == 3) {
        if (i >= COUT * 49) return;
        float mx = __uint_as_float(g_max[1]);
        float t = tanhf(W1[i]) / (2.f * mx) + 0.5f;
        g_W1f[i] = 2.f * (rintf(t * 15.f) / 15.f) - 1.f;
        return;
    }
    const float* src; __nv_bfloat16* dst; int N, K, slot;
    if (which == 1) { src = W2; dst = g_W2; N = CEXP; K = COUT; slot = 2; }
    else            { src = W3; dst = g_W3; N = COUT; K = CEXP; slot = 3; }
    if (i >= N * K) return;
    int n = i / K, k = i - n * K;
    float mx = __uint_as_float(g_max[slot]);
    float t  = tanhf(src[i]) / (2.f * mx) + 0.5f;
    __nv_bfloat16 v = __float2bfloat16(2.f * rintf(t * 15.f) - 15.f);
    dst[(size_t)(2 * k) * N + n] = v;
    dst[(size_t)(2 * k + 1) * N + n] = v;
}

// ------------- BN0 + q16 + im2col -> u8 byte planes, m-major -----------------
// block=(oh,b); stage x[b,:,2oh:2oh+2,:] (128ch x 2 x 56) in smem
__global__ void im2col8_kernel(const float* __restrict__ x,
                               const float* __restrict__ bg, const float* __restrict__ bb,
                               const float* __restrict__ bm, const float* __restrict__ bv) {
    extern __shared__ float sm[];        // xs[14336] + inv[128] + bias[128]
    float* xs   = sm;
    float* sinv = sm + 14336;
    float* sbia = sm + 14464;
    int oh = blockIdx.x, b = blockIdx.y, tid = threadIdx.x;
    for (int idx = tid; idx < 14336; idx += 256) {
        int c = idx / 112, rem = idx - c * 112;
        int dy = rem / 56, iw = rem - dy * 56;
        xs[idx] = x[(((size_t)b * CIN + c) * 56 + 2 * oh + dy) * 56 + iw];
    }
    if (tid < 128) {
        float inv = bg[tid] / sqrtf(bv[tid] + EPS_BN);
        sinv[tid] = inv;
        sbia[tid] = bb[tid] - bm[tid] * inv;
    }
    __syncthreads();
    if (tid >= 224) return;
    int ow = tid >> 3, chunk = tid & 7;      // 28 pixels x 8 chunks of 64 k
    size_t m = (size_t)b * HWOUT + oh * HOUT + ow;
    uint32_t* dh = (uint32_t*)(g_A8 + m * 1024 + chunk * 64);
    uint32_t* dl = (uint32_t*)(g_A8 + m * 1024 + 512 + chunk * 64);
    #pragma unroll 4
    for (int q = 0; q < 16; q++) {           // 4 k's per u32
        uint32_t ph = 0, pl = 0;
        #pragma unroll
        for (int j = 0; j < 4; j++) {
            int k = chunk * 64 + q * 4 + j;
            int c = k >> 2, dy = (k >> 1) & 1, dx = k & 1;
            float v = xs[c * 112 + dy * 56 + 2 * ow + dx];
            float y = fminf(fmaxf(v * sinv[c] + sbia[c], 0.f), 1.f);
            int yi = (int)rintf(y * 65535.f);
            ph |= (uint32_t)(yi >> 8) << (8 * j);
            pl |= (uint32_t)(yi & 255) << (8 * j);
        }
        dh[q] = ph;
        dl[q] = pl;
    }
}

// ------------- int8 conv1 GEMM: exact ---------------------------------------
// t0[m][n](NCHW) = (256*Ah.W + Al.W) / (65535*15)
#define I_LDK 80
#define I_PL  (128 * I_LDK)                  // 10240 B per plane
#define I_STG (3 * I_PL)                     // Ahi, Alo, B
#define I_SM  (4 * I_STG)                    // 4 stages = 122880 B

__global__ void __launch_bounds__(512, 1)
gemm_i8(const uint8_t* __restrict__ A8, const int8_t* __restrict__ W8,
        float* __restrict__ outf) {
    extern __shared__ char smem[];
    const int tid = threadIdx.x, lane = tid & 31, wid = tid >> 5;
    const int m0 = blockIdx.x * 128, n0 = blockIdx.y * 128;
    const int wm = (wid & 3) * 32, wn = (wid >> 2) * 32;
    const uint32_t sbase = (uint32_t)__cvta_generic_to_shared(smem);

    int acc[2][2][4][4];                     // [plane][mf][nf][e]
    #pragma unroll
    for (int p = 0; p < 2; p++)
        #pragma unroll
        for (int mf = 0; mf < 2; mf++)
            #pragma unroll
            for (int nf = 0; nf < 4; nf++)
                #pragma unroll
                for (int e = 0; e < 4; e++) acc[p][mf][nf][e] = 0;

    const int iters = 512 / 64;
    auto load_tile = [&](int it) {
        if (it < iters) {
            int kc = it * 64;
            uint32_t s0 = sbase + (it & 3) * I_STG;
            if (tid < 384) {
                const void* g; uint32_t d;
                if (tid < 128) {
                    g = A8 + (size_t)(m0 + tid) * 1024 + kc;
                    d = s0 + tid * I_LDK;
                } else if (tid < 256) {
                    int r = tid - 128;
                    g = A8 + (size_t)(m0 + r) * 1024 + 512 + kc;
                    d = s0 + I_PL + r * I_LDK;
                } else {
                    int r = tid - 256;
                    g = W8 + (size_t)(n0 + r) * 512 + kc;
                    d = s0 + 2 * I_PL + r * I_LDK;
                }
                cp16(d, g);
                cp16(d + 16, (const char*)g + 16);
                cp16(d + 32, (const char*)g + 32);
                cp16(d + 48, (const char*)g + 48);
            }
        }
        CP_COMMIT();
    };

    load_tile(0); load_tile(1); load_tile(2);

    for (int it = 0; it < iters; ++it) {
        asm volatile("cp.async.wait_group 2;\n");
        __syncthreads();
        load_tile(it + 3);

        uint32_t s0 = sbase + (it & 3) * I_STG;
        #pragma unroll
        for (int kf = 0; kf < 2; kf++) {
            const int acol = kf * 32 + ((lane >> 4) << 4);
            const int arow = lane & 15;
            uint32_t a[2][2][4];
            #pragma unroll
            for (int p = 0; p < 2; p++)
                #pragma unroll
                for (int mf = 0; mf < 2; mf++)
                    ldmx4(a[p][mf][0], a[p][mf][1], a[p][mf][2], a[p][mf][3],
                          s0 + p * I_PL + (wm + mf * 16 + arow) * I_LDK + acol);
            uint32_t bfr[2][4];
            const int brow = ((lane >> 4) << 3) + (lane & 7);
            const int bcol = kf * 32 + (((lane >> 3) & 1) << 4);
            #pragma unroll
            for (int nf2 = 0; nf2 < 2; nf2++)
                ldmx4(bfr[nf2][0], bfr[nf2][1], bfr[nf2][2], bfr[nf2][3],
                      s0 + 2 * I_PL + (wn + nf2 * 16 + brow) * I_LDK + bcol);
            #pragma unroll
            for (int p = 0; p < 2; p++)
                #pragma unroll
                for (int mf = 0; mf < 2; mf++)
                    #pragma unroll
                    for (int nf = 0; nf < 4; nf++)
                        imma16832(acc[p][mf][nf], a[p][mf],
                                  bfr[nf >> 1][(nf & 1) * 2], bfr[nf >> 1][(nf & 1) * 2 + 1]);
        }
    }

    const float SC2 = 1.f / (65535.f * 15.f);
    #pragma unroll
    for (int mf = 0; mf < 2; mf++) {
        #pragma unroll
        for (int nf = 0; nf < 4; nf++) {
            #pragma unroll
            for (int e = 0; e < 4; e++) {
                int m = m0 + wm + mf * 16 + (lane >> 2) + ((e >> 1) ? 8 : 0);
                int n = n0 + wn + nf * 8 + 2 * (lane & 3) + (e & 1);
                int vi = (acc[0][mf][nf][e] << 8) + acc[1][mf][nf][e];
                int b = m / HWOUT, s = m - b * HWOUT;
                outf[((size_t)b * COUT + n) * HWOUT + s] = (float)vi * SC2;
            }
        }
    }
}

// ------------- bf16 tensor-core GEMM, 4-stage (unchanged from R6) ------------
#define BM 128
#define BN 128
#define BK 32
#define LDS 136
#define STAGES 4
#define MAT_BYTES (BK * LDS * 2)
#define STG_BYTES (2 * MAT_BYTES)
#define SM_GEMM (STAGES * STG_BYTES)

template<int MODE>
__global__ void __launch_bounds__(256)
mma_gemm(const __nv_bfloat16* __restrict__ A, const __nv_bfloat16* __restrict__ B,
         int Kp, int N, float* __restrict__ outf, __nv_bfloat16* __restrict__ outp,
         const float* __restrict__ resid) {
    extern __shared__ char smem[];
    const int tid = threadIdx.x;
    const int lane = tid & 31, wid = tid >> 5;
    const int m0b = blockIdx.x * BM, n0b = blockIdx.y * BN;
    const int wm = (wid & 1) * 64;
    const int wn = (wid >> 1) * 32;

    float acc[4][4][4];
    #pragma unroll
    for (int t = 0; t < 4; t++)
        #pragma unroll
        for (int u = 0; u < 4; u++)
            #pragma unroll
            for (int e = 0; e < 4; e++) acc[t][u][e] = 0.f;

    const int r0 = tid >> 4;
    const int c0 = (tid & 15) * 8;
    const uint32_t sbase = (uint32_t)__cvta_generic_to_shared(smem);
    const uint32_t st_off = (r0 * LDS + c0) * 2;

    const int g = lane >> 3, r = lane & 7;
    const int a_row0 = ((g >> 1) << 3) + r;
    const int a_col  = wm + ((g & 1) << 3);
    const int b_row0 = ((g & 1) << 3) + r;
    const int b_col0 = wn + ((g >> 1) << 3);

    const int iters = Kp / BK;
    auto load_tile = [&](int it) {
        if (it < iters) {
            const int kb = it * BK;
            const uint32_t sa = sbase + (it % STAGES) * STG_BYTES + st_off;
            const uint32_t sbm = sa + MAT_BYTES;
            const __nv_bfloat16* ag = A + (size_t)(kb + r0) * MPIX + m0b + c0;
            const __nv_bfloat16* bg = B + (size_t)(kb + r0) * N + n0b + c0;
            cp16(sa, ag);
            cp16(sa + 16 * LDS * 2, ag + (size_t)16 * MPIX);
            cp16(sbm, bg);
            cp16(sbm + 16 * LDS * 2, bg + (size_t)16 * N);
        }
        CP_COMMIT();
    };

    load_tile(0); load_tile(1); load_tile(2);

    for (int it = 0; it < iters; ++it) {
        asm volatile("cp.async.wait_group 2;\n");
        __syncthreads();
        load_tile(it + 3);

        const uint32_t ab = sbase + (it % STAGES) * STG_BYTES;
        const uint32_t bb = ab + MAT_BYTES;
        #pragma unroll
        for (int h = 0; h < 2; ++h) {
            uint32_t af[4][4];
            #pragma unroll
            for (int t = 0; t < 4; ++t)
                ldmx4t(af[t][0], af[t][1], af[t][2], af[t][3],
                       ab + ((a_row0 + h * 16) * LDS + a_col + t * 16) * 2);
            uint32_t bfr[2][4];
            #pragma unroll
            for (int pq = 0; pq < 2; ++pq)
                ldmx4t(bfr[pq][0], bfr[pq][1], bfr[pq][2], bfr[pq][3],
                       bb + ((b_row0 + h * 16) * LDS + b_col0 + pq * 16) * 2);
            #pragma unroll
            for (int t = 0; t < 4; ++t)
                #pragma unroll
                for (int u = 0; u < 4; ++u)
                    mma16816(acc[t][u], af[t],
                             bfr[u >> 1][(u & 1) * 2], bfr[u >> 1][(u & 1) * 2 + 1]);
        }
    }

    const float SC = 1.f / 15.f;
    const int row_ = lane >> 2, col_ = (lane & 3) * 2;
    #pragma unroll
    for (int t = 0; t < 4; ++t) {
        #pragma unroll
        for (int u = 0; u < 4; ++u) {
            #pragma unroll
            for (int e = 0; e < 4; ++e) {
                int m = m0b + wm + t * 16 + row_ + ((e >> 1) ? 8 : 0);
                int n = n0b + wn + u * 8 + col_ + (e & 1);
                float v = acc[t][u][e] * SC;
                if (MODE == 1) {
                    float vr = fmaxf(v, 0.f);
                    __nv_bfloat16 h = __float2bfloat16(vr);
                    outp[(size_t)(2 * n) * MPIX + m] = h;
                    outp[(size_t)(2 * n + 1) * MPIX + m] =
                        __float2bfloat16(vr - __bfloat162float(h));
                } else {
                    int b = m / HWOUT, s = m - b * HWOUT;
                    size_t idx = ((size_t)b * COUT + n) * HWOUT + s;
                    v += resid[idx];
                    v = fminf(fmaxf(v, 0.f), 1.f);
                    outf[idx] = rintf(v * 15.f) * SC;
                }
            }
        }
    }
}

// ------------- depthwise 7x7 + BN1 -> split bf16 -----------------------------
__global__ void dwconv_kernel(const float* __restrict__ bg, const float* __restrict__ bb,
                              const float* __restrict__ bm, const float* __restrict__ bv) {
    __shared__ float tile[34 * 34];
    __shared__ float w[49];
    int bc = blockIdx.x;
    int c = bc & (COUT - 1);
    int b = bc >> 8;
    const float* plane = g_t0 + (size_t)bc * HWOUT;
    int tid = threadIdx.x;
    for (int idx = tid; idx < 34 * 34; idx += 256) {
        int rr = idx / 34, cc = idx - rr * 34;
        int ih = rr - 3, iw = cc - 3;
        tile[idx] = (ih >= 0 && ih < HOUT && iw >= 0 && iw < HOUT)
                        ? plane[ih * HOUT + iw] : 0.f;
    }
    if (tid < 49) w[tid] = g_W1f[c * 49 + tid];
    __syncthreads();
    float inv  = bg[c] / sqrtf(bv[c] + EPS_BN);
    float bias = bb[c] - bm[c] * inv;
    for (int s = tid; s < HWOUT; s += 256) {
        int oh = s / HOUT, ow = s - oh * HOUT;
        float sum = 0.f;
        #pragma unroll
        for (int i = 0; i < 7; i++)
            #pragma unroll
            for (int j = 0; j < 7; j++)
                sum = fmaf(tile[(oh + i) * 34 + ow + j], w[i * 7 + j], sum);
        float y = sum * inv + bias;
        __nv_bfloat16 h = __float2bfloat16(y);
        int m = b * HWOUT + s;
        g_t1[(size_t)(2 * c) * MPIX + m]     = h;
        g_t1[(size_t)(2 * c + 1) * MPIX + m] = __float2bfloat16(y - __bfloat162float(h));
    }
}

// ------------- launch --------------------------------------------------------
extern "C" void kernel_launch(void* const* d_in, const int* in_sizes, int n_in,
                              void* d_out, int out_size) {
    const float* x     = (const float*)d_in[0];
    const float* bn0_g = (const float*)d_in[1];
    const float* bn0_b = (const float*)d_in[2];
    const float* bn0_m = (const float*)d_in[3];
    const float* bn0_v = (const float*)d_in[4];
    const float* Wd    = (const float*)d_in[5];
    const float* W1    = (const float*)d_in[6];
    const float* bn1_g = (const float*)d_in[7];
    const float* bn1_b = (const float*)d_in[8];
    const float* bn1_m = (const float*)d_in[9];
    const float* bn1_v = (const float*)d_in[10];
    const float* W2    = (const float*)d_in[11];
    const float* W3    = (const float*)d_in[12];
    float* out = (float*)d_out;

    void *pA8, *pW8, *pT0, *pT1, *pT2, *pW2q, *pW3q;
    cudaGetSymbolAddress(&pA8, g_A8);
    cudaGetSymbolAddress(&pW8, g_W8d);
    cudaGetSymbolAddress(&pT0, g_t0);
    cudaGetSymbolAddress(&pT1, g_t1);
    cudaGetSymbolAddress(&pT2, g_t2);
    cudaGetSymbolAddress(&pW2q, g_W2);
    cudaGetSymbolAddress(&pW3q, g_W3);

    cudaFuncSetAttribute(im2col8_kernel, cudaFuncAttributeMaxDynamicSharedMemorySize, 58368);
    cudaFuncSetAttribute(gemm_i8, cudaFuncAttributeMaxDynamicSharedMemorySize, I_SM);
    cudaFuncSetAttribute(mma_gemm<1>, cudaFuncAttributeMaxDynamicSharedMemorySize, SM_GEMM);
    cudaFuncSetAttribute(mma_gemm<2>, cudaFuncAttributeMaxDynamicSharedMemorySize, SM_GEMM);

    // weight quantization
    init_max_kernel<<<1, 32>>>();
    max4_kernel<<<dim3(64, 4), 256>>>(Wd, W1, W2, W3);
    quantW_all<<<dim3(1024, 4), 256>>>(Wd, W2, W3, W1);

    // BN0 + q16 + im2col -> u8 planes
    im2col8_kernel<<<dim3(HOUT, BATCH), 256, 58368>>>(x, bn0_g, bn0_b, bn0_m, bn0_v);

    // conv1: exact int8 GEMM, M=25088, N=256, K=512 (x2 planes)
    gemm_i8<<<dim3(MPIX / 128, 2), 512, I_SM>>>(
        (const uint8_t*)pA8, (const int8_t*)pW8, (float*)pT0);

    // depthwise + BN1
    dwconv_kernel<<<BATCH * COUT, 256>>>(bn1_g, bn1_b, bn1_m, bn1_v);

    // expand: N=1024, Kp=512
    mma_gemm<1><<<dim3(MPIX / BM, CEXP / BN), 256, SM_GEMM>>>(
        (const __nv_bfloat16*)pT1, (const __nv_bfloat16*)pW2q, 2 * COUT, CEXP,
        nullptr, (__nv_bfloat16*)pT2, nullptr);

    // project: N=256, Kp=2048, + residual + q4
    mma_gemm<2><<<dim3(MPIX / BM, COUT / BN), 256, SM_GEMM>>>(
        (const __nv_bfloat16*)pT2, (const __nv_bfloat16*)pW3q, 2 * CEXP, COUT,
        out, nullptr, (const float*)pT0);
}

// round 8
// speedup vs baseline: 1.1879x; 1.1879x over previous
#include <cuda_runtime.h>
#include <cuda_bf16.h>
#include <cstdint>

#define EPS_BN 1e-5f

#define BATCH   32
#define CIN     128
#define COUT    256
#define CEXP    1024
#define HOUT    28
#define HWOUT   784
#define MPIX    25088          // BATCH*HWOUT, divisible by 128
#define KL1     512            // conv1 logical K (CIN*2*2)

// ------------- scratch (device globals) -------------------------------------
// split activations: row 2k = bf16 hi, row 2k+1 = bf16 lo of logical k-row
__device__ __nv_bfloat16 g_A [(size_t)2 * KL1  * MPIX];   // conv1 A   (51.4 MB)
__device__ float         g_t0[(size_t)BATCH * COUT * HWOUT]; // conv1 out NCHW
__device__ __nv_bfloat16 g_t1[(size_t)2 * COUT * MPIX];   // dw out    (25.7 MB)
__device__ __nv_bfloat16 g_t2[(size_t)2 * CEXP * MPIX];   // expand out(102.8 MB)
__device__ __nv_bfloat16 g_Wd[2 * KL1  * COUT];           // 15*w, dup rows
__device__ float         g_W1f[COUT * 49];
__device__ __nv_bfloat16 g_W2[2 * COUT * CEXP];
__device__ __nv_bfloat16 g_W3[2 * CEXP * COUT];
__device__ unsigned g_max[4];

// ------------- helpers -------------------------------------------------------
__device__ __forceinline__ void ldmx4t(uint32_t& r0, uint32_t& r1, uint32_t& r2,
                                       uint32_t& r3, uint32_t addr) {
    asm volatile("ldmatrix.sync.aligned.m8n8.x4.trans.shared.b16 {%0,%1,%2,%3},[%4];"
                 : "=r"(r0), "=r"(r1), "=r"(r2), "=r"(r3) : "r"(addr));
}

__device__ __forceinline__ void mma16816(float c[4], const uint32_t a[4],
                                         uint32_t b0, uint32_t b1) {
    asm volatile("mma.sync.aligned.m16n8k16.row.col.f32.bf16.bf16.f32 "
                 "{%0,%1,%2,%3},{%4,%5,%6,%7},{%8,%9},{%0,%1,%2,%3};"
                 : "+f"(c[0]), "+f"(c[1]), "+f"(c[2]), "+f"(c[3])
                 : "r"(a[0]), "r"(a[1]), "r"(a[2]), "r"(a[3]), "r"(b0), "r"(b1));
}

__device__ __forceinline__ void cp16(uint32_t s, const void* g) {
    asm volatile("cp.async.cg.shared.global [%0],[%1],16;\n" :: "r"(s), "l"(g));
}
#define CP_COMMIT() asm volatile("cp.async.commit_group;\n")

// ------------- weight quantization -------------------------------------------
__global__ void max4_kernel(const float* __restrict__ w0, const float* __restrict__ w1,
                            const float* __restrict__ w2, const float* __restrict__ w3) {
    int slot = blockIdx.y;
    const float* w; int n;
    if      (slot == 0) { w = w0; n = COUT * KL1; }
    else if (slot == 1) { w = w1; n = COUT * 49; }
    else if (slot == 2) { w = w2; n = CEXP * COUT; }
    else                { w = w3; n = COUT * CEXP; }
    float lm = 0.f;
    for (int i = blockIdx.x * blockDim.x + threadIdx.x; i < n;
         i += gridDim.x * blockDim.x)
        lm = fmaxf(lm, fabsf(tanhf(w[i])));
    #pragma unroll
    for (int o = 16; o > 0; o >>= 1)
        lm = fmaxf(lm, __shfl_xor_sync(0xffffffffu, lm, o));
    if ((threadIdx.x & 31) == 0) atomicMax(&g_max[slot], __float_as_uint(lm));
}

// y=0: Wd, y=1: W2, y=2: W3 -> scaled (15*w) bf16, [2K][N] dup rows
// y=3: W1 -> fp32 true quantized values
__global__ void quantW_all(const float* __restrict__ Wd, const float* __restrict__ W2,
                           const float* __restrict__ W3, const float* __restrict__ W1) {
    int which = blockIdx.y;
    int i = blockIdx.x * 256 + threadIdx.x;
    if (which == 3) {
        if (i >= COUT * 49) return;
        float mx = __uint_as_float(g_max[1]);
        float t = tanhf(W1[i]) / (2.f * mx) + 0.5f;
        g_W1f[i] = 2.f * (rintf(t * 15.f) / 15.f) - 1.f;
        return;
    }
    const float* src; __nv_bfloat16* dst; int N, K, slot;
    if      (which == 0) { src = Wd; dst = g_Wd; N = COUT; K = KL1;  slot = 0; }
    else if (which == 1) { src = W2; dst = g_W2; N = CEXP; K = COUT; slot = 2; }
    else                 { src = W3; dst = g_W3; N = COUT; K = CEXP; slot = 3; }
    if (i >= N * K) return;
    int n = i / K, k = i - n * K;
    float mx = __uint_as_float(g_max[slot]);
    float t  = tanhf(src[i]) / (2.f * mx) + 0.5f;
    __nv_bfloat16 v = __float2bfloat16(2.f * rintf(t * 15.f) - 15.f);  // odd int, exact
    dst[(size_t)(2 * k) * N + n] = v;
    dst[(size_t)(2 * k + 1) * N + n] = v;
}

// ------------- BN0 + q16 + im2col -> split bf16 rows -------------------------
// blockIdx.y = (c,dy) pair; thread handles both dx taps via one float2 read
__global__ void im2col_kernel(const float* __restrict__ x,
                              const float* __restrict__ bg, const float* __restrict__ bb,
                              const float* __restrict__ bm, const float* __restrict__ bv) {
    int m = blockIdx.x * 256 + threadIdx.x;   // gridDim.x = 98 -> exactly MPIX
    int cd = blockIdx.y;                      // 0..255
    int c = cd >> 1, dy = cd & 1;
    int b = m / HWOUT, s = m - b * HWOUT;
    int oh = s / HOUT, ow = s - oh * HOUT;
    float2 v2 = *(const float2*)(x + (((size_t)b * CIN + c) * 56 + oh * 2 + dy) * 56
                                   + ow * 2);
    float inv  = bg[c] / sqrtf(bv[c] + EPS_BN);
    float bias = bb[c] - bm[c] * inv;
    int kbase = 4 * c + 2 * dy;               // dx=0 -> kbase, dx=1 -> kbase+1
    #pragma unroll
    for (int dx = 0; dx < 2; dx++) {
        float v = dx ? v2.y : v2.x;
        float y = fminf(fmaxf(v * inv + bias, 0.f), 1.f);
        y = rintf(y * 65535.f) / 65535.f;
        __nv_bfloat16 h = __float2bfloat16(y);
        int k = kbase + dx;
        g_A[(size_t)(2 * k) * MPIX + m]     = h;
        g_A[(size_t)(2 * k + 1) * MPIX + m] = __float2bfloat16(y - __bfloat162float(h));
    }
}

// ------------- tensor-core GEMM, 4-stage cp.async pipeline -------------------
// C[m][n] = (1/15) * sum_{k'} A[k'][m] * B[k'][n],  Kp = k' rows
// MODE 0: write fp32 NCHW        (conv1)
// MODE 1: relu -> split bf16 [2n][M] (expand)
// MODE 2: +resid NCHW, clip, q4 -> fp32 NCHW (project)
#define BM 128
#define BN 128
#define BK 32
#define LDS 136     // bf16 elems; 272B row stride, 16B-aligned, ldmatrix conflict-free
#define STAGES 4
#define MAT_BYTES (BK * LDS * 2)          // 8704 B per matrix per stage
#define STG_BYTES (2 * MAT_BYTES)         // A + B
#define SM_GEMM (STAGES * STG_BYTES)      // 69632 B

template<int MODE>
__global__ void __launch_bounds__(256)
mma_gemm(const __nv_bfloat16* __restrict__ A, const __nv_bfloat16* __restrict__ B,
         int Kp, int N, float* __restrict__ outf, __nv_bfloat16* __restrict__ outp,
         const float* __restrict__ resid) {
    extern __shared__ char smem[];
    const int tid = threadIdx.x;
    const int lane = tid & 31, wid = tid >> 5;
    const int m0b = blockIdx.x * BM, n0b = blockIdx.y * BN;
    const int wm = (wid & 1) * 64;
    const int wn = (wid >> 1) * 32;

    float acc[4][4][4];
    #pragma unroll
    for (int t = 0; t < 4; t++)
        #pragma unroll
        for (int u = 0; u < 4; u++)
            #pragma unroll
            for (int e = 0; e < 4; e++) acc[t][u][e] = 0.f;

    const int r0 = tid >> 4;          // rows 0..15, +16
    const int c0 = (tid & 15) * 8;    // bf16 col

    const uint32_t sbase = (uint32_t)__cvta_generic_to_shared(smem);
    const uint32_t st_off = (r0 * LDS + c0) * 2;

    const int g = lane >> 3, r = lane & 7;
    const int a_row0 = ((g >> 1) << 3) + r;
    const int a_col  = wm + ((g & 1) << 3);
    const int b_row0 = ((g & 1) << 3) + r;
    const int b_col0 = wn + ((g >> 1) << 3);

    const int iters = Kp / BK;

    auto load_tile = [&](int it) {
        if (it < iters) {
            const int kb = it * BK;
            const uint32_t sa = sbase + (it % STAGES) * STG_BYTES + st_off;
            const uint32_t sbm = sa + MAT_BYTES;
            const __nv_bfloat16* ag = A + (size_t)(kb + r0) * MPIX + m0b + c0;
            const __nv_bfloat16* bg = B + (size_t)(kb + r0) * N + n0b + c0;
            cp16(sa, ag);
            cp16(sa + 16 * LDS * 2, ag + (size_t)16 * MPIX);
            cp16(sbm, bg);
            cp16(sbm + 16 * LDS * 2, bg + (size_t)16 * N);
        }
        CP_COMMIT();   // always commit to keep group count invariant
    };

    load_tile(0);
    load_tile(1);
    load_tile(2);

    for (int it = 0; it < iters; ++it) {
        asm volatile("cp.async.wait_group 2;\n");
        __syncthreads();
        load_tile(it + 3);   // overwrites slot of tile it-1 (compute done last iter)

        const uint32_t ab = sbase + (it % STAGES) * STG_BYTES;
        const uint32_t bb = ab + MAT_BYTES;
        #pragma unroll
        for (int h = 0; h < 2; ++h) {
            uint32_t af[4][4];
            #pragma unroll
            for (int t = 0; t < 4; ++t)
                ldmx4t(af[t][0], af[t][1], af[t][2], af[t][3],
                       ab + ((a_row0 + h * 16) * LDS + a_col + t * 16) * 2);
            uint32_t bfr[2][4];
            #pragma unroll
            for (int pq = 0; pq < 2; ++pq)
                ldmx4t(bfr[pq][0], bfr[pq][1], bfr[pq][2], bfr[pq][3],
                       bb + ((b_row0 + h * 16) * LDS + b_col0 + pq * 16) * 2);
            #pragma unroll
            for (int t = 0; t < 4; ++t)
                #pragma unroll
                for (int u = 0; u < 4; ++u)
                    mma16816(acc[t][u], af[t],
                             bfr[u >> 1][(u & 1) * 2], bfr[u >> 1][(u & 1) * 2 + 1]);
        }
    }

    // epilogue
    const float SC = 1.f / 15.f;
    const int row_ = lane >> 2, col_ = (lane & 3) * 2;
    #pragma unroll
    for (int t = 0; t < 4; ++t) {
        #pragma unroll
        for (int u = 0; u < 4; ++u) {
            #pragma unroll
            for (int e = 0; e < 4; ++e) {
                int m = m0b + wm + t * 16 + row_ + ((e >> 1) ? 8 : 0);
                int n = n0b + wn + u * 8 + col_ + (e & 1);
                float v = acc[t][u][e] * SC;
                if (MODE == 0) {
                    int b = m / HWOUT, s = m - b * HWOUT;
                    outf[((size_t)b * COUT + n) * HWOUT + s] = v;
                } else if (MODE == 1) {
                    float vr = fmaxf(v, 0.f);
                    __nv_bfloat16 h = __float2bfloat16(vr);
                    outp[(size_t)(2 * n) * MPIX + m] = h;
                    outp[(size_t)(2 * n + 1) * MPIX + m] =
                        __float2bfloat16(vr - __bfloat162float(h));
                } else {
                    int b = m / HWOUT, s = m - b * HWOUT;
                    size_t idx = ((size_t)b * COUT + n) * HWOUT + s;
                    v += resid[idx];
                    v = fminf(fmaxf(v, 0.f), 1.f);
                    outf[idx] = rintf(v * 15.f) * SC;
                }
            }
        }
    }
}

// ------------- depthwise 7x7 + BN1 -> split bf16 -----------------------------
__global__ void dwconv_kernel(const float* __restrict__ bg, const float* __restrict__ bb,
                              const float* __restrict__ bm, const float* __restrict__ bv) {
    __shared__ float tile[34 * 34];
    __shared__ float w[49];
    int bc = blockIdx.x;
    int c = bc & (COUT - 1);
    int b = bc >> 8;
    const float* plane = g_t0 + (size_t)bc * HWOUT;
    int tid = threadIdx.x;
    for (int idx = tid; idx < 34 * 34; idx += 256) {
        int rr = idx / 34, cc = idx - rr * 34;
        int ih = rr - 3, iw = cc - 3;
        tile[idx] = (ih >= 0 && ih < HOUT && iw >= 0 && iw < HOUT)
                        ? plane[ih * HOUT + iw] : 0.f;
    }
    if (tid < 49) w[tid] = g_W1f[c * 49 + tid];
    __syncthreads();
    float inv  = bg[c] / sqrtf(bv[c] + EPS_BN);
    float bias = bb[c] - bm[c] * inv;
    for (int s = tid; s < HWOUT; s += 256) {
        int oh = s / HOUT, ow = s - oh * HOUT;
        float sum = 0.f;
        #pragma unroll
        for (int i = 0; i < 7; i++)
            #pragma unroll
            for (int j = 0; j < 7; j++)
                sum = fmaf(tile[(oh + i) * 34 + ow + j], w[i * 7 + j], sum);
        float y = sum * inv + bias;
        __nv_bfloat16 h = __float2bfloat16(y);
        int m = b * HWOUT + s;
        g_t1[(size_t)(2 * c) * MPIX + m]     = h;
        g_t1[(size_t)(2 * c + 1) * MPIX + m] = __float2bfloat16(y - __bfloat162float(h));
    }
}

// ------------- launch --------------------------------------------------------
extern "C" void kernel_launch(void* const* d_in, const int* in_sizes, int n_in,
                              void* d_out, int out_size) {
    const float* x     = (const float*)d_in[0];
    const float* bn0_g = (const float*)d_in[1];
    const float* bn0_b = (const float*)d_in[2];
    const float* bn0_m = (const float*)d_in[3];
    const float* bn0_v = (const float*)d_in[4];
    const float* Wd    = (const float*)d_in[5];
    const float* W1    = (const float*)d_in[6];
    const float* bn1_g = (const float*)d_in[7];
    const float* bn1_b = (const float*)d_in[8];
    const float* bn1_m = (const float*)d_in[9];
    const float* bn1_v = (const float*)d_in[10];
    const float* W2    = (const float*)d_in[11];
    const float* W3    = (const float*)d_in[12];
    float* out = (float*)d_out;

    void *pA, *pT0, *pT1, *pT2, *pWd, *pW2, *pW3, *pMax;
    cudaGetSymbolAddress(&pA,  g_A);
    cudaGetSymbolAddress(&pT0, g_t0);
    cudaGetSymbolAddress(&pT1, g_t1);
    cudaGetSymbolAddress(&pT2, g_t2);
    cudaGetSymbolAddress(&pWd, g_Wd);
    cudaGetSymbolAddress(&pW2, g_W2);
    cudaGetSymbolAddress(&pW3, g_W3);
    cudaGetSymbolAddress(&pMax, g_max);

    cudaFuncSetAttribute(mma_gemm<0>, cudaFuncAttributeMaxDynamicSharedMemorySize, SM_GEMM);
    cudaFuncSetAttribute(mma_gemm<1>, cudaFuncAttributeMaxDynamicSharedMemorySize, SM_GEMM);
    cudaFuncSetAttribute(mma_gemm<2>, cudaFuncAttributeMaxDynamicSharedMemorySize, SM_GEMM);

    // weight quantization (memset + 2 kernels)
    cudaMemsetAsync(pMax, 0, 16);
    max4_kernel<<<dim3(64, 4), 256>>>(Wd, W1, W2, W3);
    quantW_all<<<dim3(1024, 4), 256>>>(Wd, W2, W3, W1);

    // BN0 + q16 + im2col (split bf16), float2 coalesced reads
    im2col_kernel<<<dim3(98, 256), 256>>>(x, bn0_g, bn0_b, bn0_m, bn0_v);

    // conv1: M=25088, N=256, Kp=1024
    mma_gemm<0><<<dim3(MPIX / BM, COUT / BN), 256, SM_GEMM>>>(
        (const __nv_bfloat16*)pA, (const __nv_bfloat16*)pWd, 2 * KL1, COUT,
        (float*)pT0, nullptr, nullptr);

    // depthwise + BN1
    dwconv_kernel<<<BATCH * COUT, 256>>>(bn1_g, bn1_b, bn1_m, bn1_v);

    // expand: N=1024, Kp=512
    mma_gemm<1><<<dim3(MPIX / BM, CEXP / BN), 256, SM_GEMM>>>(
        (const __nv_bfloat16*)pT1, (const __nv_bfloat16*)pW2, 2 * COUT, CEXP,
        nullptr, (__nv_bfloat16*)pT2, nullptr);

    // project: N=256, Kp=2048, + residual + q4
    mma_gemm<2><<<dim3(MPIX / BM, COUT / BN), 256, SM_GEMM>>>(
        (const __nv_bfloat16*)pT2, (const __nv_bfloat16*)pW3, 2 * CEXP, COUT,
        out, nullptr, (const float*)pT0);
}